// round 15
// baseline (speedup 1.0000x reference)
#include <cuda_runtime.h>
#include <cuda_bf16.h>
#include <cstdint>
#include <cstddef>

#define N0 2000000
#define N1 200000
#define N2 16384
#define E0 3200000
#define E1 262144
#define SPLIT 200064   // 1563*128; DUAL covers [0,SPLIT); plain2 covers [SPLIT,N0) = 7031*256 rows

// Scratch (device globals: allocation-free rule)
__device__ __nv_bfloat16 g_y[(size_t)N0 * 32];   // 128 MB, bf16
__device__ float g_yr[(size_t)N1 * 32];          // x[:N1] @ W1r^T, fp32
__device__ float g_h[(size_t)N1 * 32];
__device__ float g_agg0[(size_t)N1 * 32];
__device__ float g_agg1[(size_t)N2 * 32];
__device__ float g_cnt0[N1];
__device__ float g_cnt1[N2];

__device__ __forceinline__ uint32_t pack_bf16x2(float lo, float hi) {
    uint32_t r;
    asm("cvt.rn.bf16x2.f32 %0, %1, %2;" : "=r"(r) : "f"(hi), "f"(lo));
    return r;
}
__device__ __forceinline__ float bf_lo(uint32_t w) { return __uint_as_float(w << 16); }
__device__ __forceinline__ float bf_hi(uint32_t w) { return __uint_as_float(w & 0xffff0000u); }

__device__ __forceinline__ void mma16816(float* c, const uint32_t* a, const uint32_t* b) {
    asm volatile(
        "mma.sync.aligned.m16n8k16.row.col.f32.bf16.bf16.f32 "
        "{%0,%1,%2,%3}, {%4,%5,%6,%7}, {%8,%9}, {%0,%1,%2,%3};"
        : "+f"(c[0]), "+f"(c[1]), "+f"(c[2]), "+f"(c[3])
        : "r"(a[0]), "r"(a[1]), "r"(a[2]), "r"(a[3]), "r"(b[0]), "r"(b[1]));
}

// Shared helper: build permuted B fragment tables for one weight matrix
__device__ __forceinline__ void build_B(const float* __restrict__ W,
                                        uint32_t (*sBhi)[4][32][2], uint32_t (*sBlo)[4][32][2],
                                        int tid) {
    for (int i = tid; i < 1024; i += 256) {
        int l = i & 31, nt = (i >> 5) & 3, kt = i >> 7;
        int n = nt * 8 + (l >> 2);
        int k0 = kt * 16 + (l & 3) * 4;
        float4 w = *reinterpret_cast<const float4*>(W + n * 128 + k0);
        uint32_t h0 = pack_bf16x2(w.x, w.y);
        uint32_t h1 = pack_bf16x2(w.z, w.w);
        sBhi[kt][nt][l][0] = h0;
        sBhi[kt][nt][l][1] = h1;
        sBlo[kt][nt][l][0] = pack_bf16x2(w.x - bf_lo(h0), w.y - bf_hi(h0));
        sBlo[kt][nt][l][1] = pack_bf16x2(w.z - bf_lo(h1), w.w - bf_hi(h1));
    }
}

__device__ __forceinline__ void split_a(const float4& f, uint32_t& hi, uint32_t& lo2,
                                        uint32_t& hi2, uint32_t& lo3) {
    // packs (f.x,f.y) and (f.z,f.w) into hi words + residuals
    hi  = pack_bf16x2(f.x, f.y);
    hi2 = pack_bf16x2(f.z, f.w);
    lo2 = pack_bf16x2(f.x - bf_lo(hi),  f.y - bf_hi(hi));
    lo3 = pack_bf16x2(f.z - bf_lo(hi2), f.w - bf_hi(hi2));
}

// ---------------- plain GEMM, 2 tiles/warp (256 rows/block): y = x @ Wl^T (bf16) ----------------
__global__ void __launch_bounds__(256) gemm2_kernel(
    const float* __restrict__ x, const float* __restrict__ Wl,
    int base, int M, __nv_bfloat16* __restrict__ obf)
{
    __shared__ uint32_t sBhi[8][4][32][2];
    __shared__ uint32_t sBlo[8][4][32][2];

    const int tid = threadIdx.x;
    const int warp = tid >> 5, lane = tid & 31;
    const int gid = lane >> 2, tig = lane & 3;

    build_B(Wl, sBhi, sBlo, tid);
    __syncthreads();

    int r0 = base + blockIdx.x * 256 + warp * 32 + gid;   // tile0: rows r0, r0+8
    int r2 = r0 + 16;                                     // tile1: rows r2, r2+8
    const float* xp[4];
    xp[0] = x + (size_t)(r0      < M ? r0      : M - 1) * 128;
    xp[1] = x + (size_t)(r0 + 8  < M ? r0 + 8  : M - 1) * 128;
    xp[2] = x + (size_t)(r2      < M ? r2      : M - 1) * 128;
    xp[3] = x + (size_t)(r2 + 8  < M ? r2 + 8  : M - 1) * 128;

    float acc[2][4][4];
#pragma unroll
    for (int t = 0; t < 2; ++t)
#pragma unroll
        for (int nt = 0; nt < 4; ++nt)
#pragma unroll
            for (int j = 0; j < 4; ++j) acc[t][nt][j] = 0.f;

#pragma unroll
    for (int kt = 0; kt < 8; ++kt) {
        int c0 = kt * 16 + tig * 4;
        float4 f0 = *reinterpret_cast<const float4*>(xp[0] + c0);
        float4 f1 = *reinterpret_cast<const float4*>(xp[1] + c0);
        float4 f2 = *reinterpret_cast<const float4*>(xp[2] + c0);
        float4 f3 = *reinterpret_cast<const float4*>(xp[3] + c0);

        uint32_t ahi0[4], alo0[4], ahi1[4], alo1[4];
        split_a(f0, ahi0[0], alo0[0], ahi0[2], alo0[2]);
        split_a(f1, ahi0[1], alo0[1], ahi0[3], alo0[3]);
        split_a(f2, ahi1[0], alo1[0], ahi1[2], alo1[2]);
        split_a(f3, ahi1[1], alo1[1], ahi1[3], alo1[3]);

#pragma unroll
        for (int nt = 0; nt < 4; ++nt) {
            uint32_t bh[2], bl[2];
            bh[0] = sBhi[kt][nt][lane][0];
            bh[1] = sBhi[kt][nt][lane][1];
            bl[0] = sBlo[kt][nt][lane][0];
            bl[1] = sBlo[kt][nt][lane][1];
            mma16816(acc[0][nt], ahi0, bh);
            mma16816(acc[0][nt], ahi0, bl);
            mma16816(acc[0][nt], alo0, bh);
            mma16816(acc[1][nt], ahi1, bh);
            mma16816(acc[1][nt], ahi1, bl);
            mma16816(acc[1][nt], alo1, bh);
        }
    }

#pragma unroll
    for (int t = 0; t < 2; ++t) {
        int ra = r0 + t * 16, rb = ra + 8;
        if (ra < M) {
            uint32_t* o = reinterpret_cast<uint32_t*>(obf + (size_t)ra * 32) + tig;
#pragma unroll
            for (int nt = 0; nt < 4; ++nt) o[nt * 4] = pack_bf16x2(acc[t][nt][0], acc[t][nt][1]);
        }
        if (rb < M) {
            uint32_t* o = reinterpret_cast<uint32_t*>(obf + (size_t)rb * 32) + tig;
#pragma unroll
            for (int nt = 0; nt < 4; ++nt) o[nt * 4] = pack_bf16x2(acc[t][nt][2], acc[t][nt][3]);
        }
    }
}

// ---------------- DUAL GEMM (rows [0,SPLIT)): y bf16 + yr fp32 ----------------
__global__ void __launch_bounds__(256) gemm_dual_kernel(
    const float* __restrict__ x, const float* __restrict__ Wl,
    const float* __restrict__ Wr, int M,
    __nv_bfloat16* __restrict__ obf, float* __restrict__ oyr)
{
    __shared__ uint32_t sBhi[8][4][32][2];
    __shared__ uint32_t sBlo[8][4][32][2];
    __shared__ uint32_t sB2hi[8][4][32][2];
    __shared__ uint32_t sB2lo[8][4][32][2];

    const int tid = threadIdx.x;
    const int warp = tid >> 5, lane = tid & 31;
    const int gid = lane >> 2, tig = lane & 3;

    build_B(Wl, sBhi, sBlo, tid);
    build_B(Wr, sB2hi, sB2lo, tid);
    __syncthreads();

    int r0 = blockIdx.x * 128 + warp * 16 + gid;
    int r1 = r0 + 8;
    const float* x0 = x + (size_t)(r0 < M ? r0 : M - 1) * 128;
    const float* x1 = x + (size_t)(r1 < M ? r1 : M - 1) * 128;

    float acc[4][4], acc2[4][4];
#pragma unroll
    for (int nt = 0; nt < 4; ++nt)
#pragma unroll
        for (int j = 0; j < 4; ++j) { acc[nt][j] = 0.f; acc2[nt][j] = 0.f; }

#pragma unroll
    for (int kt = 0; kt < 8; ++kt) {
        int c0 = kt * 16 + tig * 4;
        float4 f0 = *reinterpret_cast<const float4*>(x0 + c0);
        float4 f1 = *reinterpret_cast<const float4*>(x1 + c0);

        uint32_t ahi[4], alo[4];
        split_a(f0, ahi[0], alo[0], ahi[2], alo[2]);
        split_a(f1, ahi[1], alo[1], ahi[3], alo[3]);

#pragma unroll
        for (int nt = 0; nt < 4; ++nt) {
            uint32_t bh[2], bl[2], ch[2], cl[2];
            bh[0] = sBhi[kt][nt][lane][0];  bh[1] = sBhi[kt][nt][lane][1];
            bl[0] = sBlo[kt][nt][lane][0];  bl[1] = sBlo[kt][nt][lane][1];
            ch[0] = sB2hi[kt][nt][lane][0]; ch[1] = sB2hi[kt][nt][lane][1];
            cl[0] = sB2lo[kt][nt][lane][0]; cl[1] = sB2lo[kt][nt][lane][1];
            mma16816(acc[nt], ahi, bh);
            mma16816(acc[nt], ahi, bl);
            mma16816(acc[nt], alo, bh);
            mma16816(acc2[nt], ahi, ch);
            mma16816(acc2[nt], ahi, cl);
            mma16816(acc2[nt], alo, ch);
        }
    }

    if (r0 < M) {
        uint32_t* o = reinterpret_cast<uint32_t*>(obf + (size_t)r0 * 32) + tig;
#pragma unroll
        for (int nt = 0; nt < 4; ++nt) o[nt * 4] = pack_bf16x2(acc[nt][0], acc[nt][1]);
    }
    if (r1 < M) {
        uint32_t* o = reinterpret_cast<uint32_t*>(obf + (size_t)r1 * 32) + tig;
#pragma unroll
        for (int nt = 0; nt < 4; ++nt) o[nt * 4] = pack_bf16x2(acc[nt][2], acc[nt][3]);
    }
    if (r0 < N1) {
        float* o = oyr + (size_t)r0 * 32 + tig * 2;
#pragma unroll
        for (int nt = 0; nt < 4; ++nt)
            *reinterpret_cast<float2*>(o + nt * 8) = make_float2(acc2[nt][0], acc2[nt][1]);
    }
    if (r1 < N1) {
        float* o = oyr + (size_t)r1 * 32 + tig * 2;
#pragma unroll
        for (int nt = 0; nt < 4; ++nt)
            *reinterpret_cast<float2*>(o + nt * 8) = make_float2(acc2[nt][2], acc2[nt][3]);
    }
}

// ---------------- bf16 edge scatter: 8 threads/edge, 8-edge MLP ----------------
__global__ void scatter_bf16_kernel(const int* __restrict__ src, const int* __restrict__ dst,
                                    const __nv_bfloat16* __restrict__ feat,
                                    float* __restrict__ agg, float* __restrict__ cnt, int E) {
    int g = blockIdx.x * blockDim.x + threadIdx.x;
    int oct = E >> 3;
    int e = g >> 3, part = g & 7;
    if (e >= oct) return;
    int s[8], d[8];
#pragma unroll
    for (int j = 0; j < 8; ++j) {
        s[j] = __ldg(src + e + j * oct);
        d[j] = __ldg(dst + e + j * oct);
    }
    uint2 v[8];
#pragma unroll
    for (int j = 0; j < 8; ++j)
        v[j] = reinterpret_cast<const uint2*>(feat + (size_t)s[j] * 32)[part];
#pragma unroll
    for (int j = 0; j < 8; ++j) {
        float4 f = make_float4(bf_lo(v[j].x), bf_hi(v[j].x), bf_lo(v[j].y), bf_hi(v[j].y));
        atomicAdd(reinterpret_cast<float4*>(agg + (size_t)d[j] * 32 + part * 4), f);
    }
    if (part == 0) {
#pragma unroll
        for (int j = 0; j < 8; ++j) atomicAdd(cnt + d[j], 1.0f);
    }
}

// ---------------- fp32 edge scatter (8 threads/edge, 4-edge MLP) — for h/E1 ----------------
__global__ void scatter_kernel(const int* __restrict__ src, const int* __restrict__ dst,
                               const float* __restrict__ feat, float* __restrict__ agg,
                               float* __restrict__ cnt, int E) {
    int g = blockIdx.x * blockDim.x + threadIdx.x;
    int quart = E >> 2;
    int e = g >> 3, part = g & 7;
    if (e >= quart) return;
    int s[4], d[4];
#pragma unroll
    for (int j = 0; j < 4; ++j) {
        s[j] = __ldg(src + e + j * quart);
        d[j] = __ldg(dst + e + j * quart);
    }
    float4 v[4];
#pragma unroll
    for (int j = 0; j < 4; ++j)
        v[j] = *reinterpret_cast<const float4*>(feat + (size_t)s[j] * 32 + part * 4);
#pragma unroll
    for (int j = 0; j < 4; ++j)
        atomicAdd(reinterpret_cast<float4*>(agg + (size_t)d[j] * 32 + part * 4), v[j]);
    if (part == 0) {
#pragma unroll
        for (int j = 0; j < 4; ++j) atomicAdd(cnt + d[j], 1.0f);
    }
}

// ---------------- h = relu(agg0/cnt + yr), elementwise float4 ----------------
__global__ void relu_combine_kernel(const float* __restrict__ agg, const float* __restrict__ cnt,
                                    const float* __restrict__ yr, float* __restrict__ h) {
    int i = blockIdx.x * blockDim.x + threadIdx.x;   // float4 index, N1*8 total
    if (i >= N1 * 8) return;
    int row = i >> 3;
    float inv = 1.0f / fmaxf(__ldg(cnt + row), 1.0f);
    float4 a = reinterpret_cast<const float4*>(agg)[i];
    float4 v = reinterpret_cast<const float4*>(yr)[i];
    float4 r;
    r.x = fmaxf(fmaf(a.x, inv, v.x), 0.f);
    r.y = fmaxf(fmaf(a.y, inv, v.y), 0.f);
    r.z = fmaxf(fmaf(a.z, inv, v.z), 0.f);
    r.w = fmaxf(fmaf(a.w, inv, v.w), 0.f);
    reinterpret_cast<float4*>(h)[i] = r;
}

// ---------------- layer-1 combine ----------------
__global__ void final_kernel(const float* __restrict__ agg1, const float* __restrict__ cnt1,
                             const float* __restrict__ h, const float* __restrict__ W2l,
                             const float* __restrict__ W2r, float* __restrict__ out) {
    __shared__ float s2l[32 * 64];
    __shared__ float s2r[32 * 64];
    int tid = threadIdx.x;
    for (int idx = tid; idx < 2048; idx += 256) {
        int c = idx >> 5, k = idx & 31;
        s2l[k * 64 + c] = W2l[idx];
        s2r[k * 64 + c] = W2r[idx];
    }
    __syncthreads();
    int i = blockIdx.x * 4 + (tid >> 6);
    int c = tid & 63;
    float inv = 1.0f / fmaxf(__ldg(cnt1 + i), 1.0f);
    const float* ag = agg1 + (size_t)i * 32;
    const float* hh = h + (size_t)i * 32;
    float s = 0.f;
#pragma unroll
    for (int k = 0; k < 32; ++k)
        s = fmaf(__ldg(ag + k) * inv, s2l[k * 64 + c], fmaf(__ldg(hh + k), s2r[k * 64 + c], s));
    out[(size_t)i * 64 + c] = s;
}

extern "C" void kernel_launch(void* const* d_in, const int* in_sizes, int n_in,
                              void* d_out, int out_size) {
    const float* x   = (const float*)d_in[0];
    const float* W1l = (const float*)d_in[1];
    const float* W1r = (const float*)d_in[2];
    const float* W2l = (const float*)d_in[3];
    const float* W2r = (const float*)d_in[4];
    const int* es0   = (const int*)d_in[5];
    const int* ed0   = (const int*)d_in[6];
    const int* es1   = (const int*)d_in[7];
    const int* ed1   = (const int*)d_in[8];
    float* out = (float*)d_out;

    __nv_bfloat16* y;
    float *yr, *h, *agg0, *agg1, *cnt0, *cnt1;
    cudaGetSymbolAddress((void**)&y,    g_y);
    cudaGetSymbolAddress((void**)&yr,   g_yr);
    cudaGetSymbolAddress((void**)&h,    g_h);
    cudaGetSymbolAddress((void**)&agg0, g_agg0);
    cudaGetSymbolAddress((void**)&agg1, g_agg1);
    cudaGetSymbolAddress((void**)&cnt0, g_cnt0);
    cudaGetSymbolAddress((void**)&cnt1, g_cnt1);

    cudaMemsetAsync(agg0, 0, sizeof(float) * (size_t)N1 * 32, 0);
    cudaMemsetAsync(cnt0, 0, sizeof(float) * N1, 0);
    cudaMemsetAsync(agg1, 0, sizeof(float) * (size_t)N2 * 32, 0);
    cudaMemsetAsync(cnt1, 0, sizeof(float) * N2, 0);

    // DUAL: rows [0, SPLIT) -> y(bf16) + yr(fp32); plain2: rows [SPLIT, N0), 256 rows/block
    gemm_dual_kernel<<<SPLIT / 128, 256>>>(x, W1l, W1r, N0, y, yr);
    gemm2_kernel<<<(N0 - SPLIT) / 256, 256>>>(x, W1l, SPLIT, N0, y);
    // sum y over E0 edges
    scatter_bf16_kernel<<<(int)(((size_t)(E0 / 8) * 8 + 255) / 256), 256>>>(es0, ed0, y, agg0, cnt0, E0);
    // h = relu(agg0/cnt + yr)
    relu_combine_kernel<<<(N1 * 8 + 255) / 256, 256>>>(agg0, cnt0, yr, h);
    // layer-1 aggregation + combine
    scatter_kernel<<<(int)(((size_t)(E1 / 4) * 8 + 255) / 256), 256>>>(es1, ed1, h, agg1, cnt1, E1);
    final_kernel<<<N2 / 4, 256>>>(agg1, cnt1, h, W2l, W2r, out);
}

// round 16
// speedup vs baseline: 1.0475x; 1.0475x over previous
#include <cuda_runtime.h>
#include <cuda_bf16.h>
#include <cstdint>
#include <cstddef>

#define N0 2000000
#define N1 200000
#define N2 16384
#define E0 3200000
#define E1 262144
#define SPLIT 200064   // 1563*128; DUAL covers [0,SPLIT); plain covers [SPLIT,N0)

// Scratch (device globals: allocation-free rule)
__device__ __nv_bfloat16 g_y[(size_t)N0 * 32];   // 128 MB, bf16
__device__ float g_yr[(size_t)N1 * 32];          // x[:N1] @ W1r^T, fp32
__device__ float g_h[(size_t)N1 * 32];
__device__ float g_agg0[(size_t)N1 * 32];
__device__ float g_agg1[(size_t)N2 * 32];
__device__ float g_cnt0[N1];
__device__ float g_cnt1[N2];

__device__ __forceinline__ uint32_t pack_bf16x2(float lo, float hi) {
    uint32_t r;
    asm("cvt.rn.bf16x2.f32 %0, %1, %2;" : "=r"(r) : "f"(hi), "f"(lo));
    return r;
}
__device__ __forceinline__ float bf_lo(uint32_t w) { return __uint_as_float(w << 16); }
__device__ __forceinline__ float bf_hi(uint32_t w) { return __uint_as_float(w & 0xffff0000u); }

__device__ __forceinline__ void mma16816(float* c, const uint32_t* a, const uint32_t* b) {
    asm volatile(
        "mma.sync.aligned.m16n8k16.row.col.f32.bf16.bf16.f32 "
        "{%0,%1,%2,%3}, {%4,%5,%6,%7}, {%8,%9}, {%0,%1,%2,%3};"
        : "+f"(c[0]), "+f"(c[1]), "+f"(c[2]), "+f"(c[3])
        : "r"(a[0]), "r"(a[1]), "r"(a[2]), "r"(a[3]), "r"(b[0]), "r"(b[1]));
}

// Build permuted B fragment tables for one weight matrix
__device__ __forceinline__ void build_B(const float* __restrict__ W,
                                        uint32_t (*sBhi)[4][32][2], uint32_t (*sBlo)[4][32][2],
                                        int tid) {
    for (int i = tid; i < 1024; i += 256) {
        int l = i & 31, nt = (i >> 5) & 3, kt = i >> 7;
        int n = nt * 8 + (l >> 2);
        int k0 = kt * 16 + (l & 3) * 4;
        float4 w = *reinterpret_cast<const float4*>(W + n * 128 + k0);
        uint32_t h0 = pack_bf16x2(w.x, w.y);
        uint32_t h1 = pack_bf16x2(w.z, w.w);
        sBhi[kt][nt][l][0] = h0;
        sBhi[kt][nt][l][1] = h1;
        sBlo[kt][nt][l][0] = pack_bf16x2(w.x - bf_lo(h0), w.y - bf_hi(h0));
        sBlo[kt][nt][l][1] = pack_bf16x2(w.z - bf_lo(h1), w.w - bf_hi(h1));
    }
}

__device__ __forceinline__ void split_a(const float4& f, uint32_t& hi, uint32_t& lo2,
                                        uint32_t& hi2, uint32_t& lo3) {
    hi  = pack_bf16x2(f.x, f.y);
    hi2 = pack_bf16x2(f.z, f.w);
    lo2 = pack_bf16x2(f.x - bf_lo(hi),  f.y - bf_hi(hi));
    lo3 = pack_bf16x2(f.z - bf_lo(hi2), f.w - bf_hi(hi2));
}

// ---------------- plain GEMM (rows [base, base+grid*128)): y = x @ Wl^T (bf16) ----------------
// __launch_bounds__(256, 5): cap regs at 48 -> 5 CTAs/SM (62.5% occ) for latency hiding.
__global__ void __launch_bounds__(256, 5) gemm_plain_kernel(
    const float* __restrict__ x, const float* __restrict__ Wl,
    int base, int M, __nv_bfloat16* __restrict__ obf)
{
    __shared__ uint32_t sBhi[8][4][32][2];
    __shared__ uint32_t sBlo[8][4][32][2];

    const int tid = threadIdx.x;
    const int warp = tid >> 5, lane = tid & 31;
    const int gid = lane >> 2, tig = lane & 3;

    build_B(Wl, sBhi, sBlo, tid);
    __syncthreads();

    int r0 = base + blockIdx.x * 128 + warp * 16 + gid;
    int r1 = r0 + 8;
    const float* x0 = x + (size_t)(r0 < M ? r0 : M - 1) * 128;
    const float* x1 = x + (size_t)(r1 < M ? r1 : M - 1) * 128;

    float acc[4][4];
#pragma unroll
    for (int nt = 0; nt < 4; ++nt)
#pragma unroll
        for (int j = 0; j < 4; ++j) acc[nt][j] = 0.f;

#pragma unroll
    for (int kt = 0; kt < 8; ++kt) {
        int c0 = kt * 16 + tig * 4;
        float4 f0 = *reinterpret_cast<const float4*>(x0 + c0);
        float4 f1 = *reinterpret_cast<const float4*>(x1 + c0);

        uint32_t ahi[4], alo[4];
        split_a(f0, ahi[0], alo[0], ahi[2], alo[2]);
        split_a(f1, ahi[1], alo[1], ahi[3], alo[3]);

#pragma unroll
        for (int nt = 0; nt < 4; ++nt) {
            uint32_t bh[2], bl[2];
            bh[0] = sBhi[kt][nt][lane][0];
            bh[1] = sBhi[kt][nt][lane][1];
            bl[0] = sBlo[kt][nt][lane][0];
            bl[1] = sBlo[kt][nt][lane][1];
            mma16816(acc[nt], ahi, bh);
            mma16816(acc[nt], ahi, bl);
            mma16816(acc[nt], alo, bh);
        }
    }

    if (r0 < M) {
        uint32_t* o = reinterpret_cast<uint32_t*>(obf + (size_t)r0 * 32) + tig;
#pragma unroll
        for (int nt = 0; nt < 4; ++nt) o[nt * 4] = pack_bf16x2(acc[nt][0], acc[nt][1]);
    }
    if (r1 < M) {
        uint32_t* o = reinterpret_cast<uint32_t*>(obf + (size_t)r1 * 32) + tig;
#pragma unroll
        for (int nt = 0; nt < 4; ++nt) o[nt * 4] = pack_bf16x2(acc[nt][2], acc[nt][3]);
    }
}

// ---------------- DUAL GEMM (rows [0,SPLIT)): y bf16 + yr fp32 ----------------
__global__ void __launch_bounds__(256) gemm_dual_kernel(
    const float* __restrict__ x, const float* __restrict__ Wl,
    const float* __restrict__ Wr, int M,
    __nv_bfloat16* __restrict__ obf, float* __restrict__ oyr)
{
    __shared__ uint32_t sBhi[8][4][32][2];
    __shared__ uint32_t sBlo[8][4][32][2];
    __shared__ uint32_t sB2hi[8][4][32][2];
    __shared__ uint32_t sB2lo[8][4][32][2];

    const int tid = threadIdx.x;
    const int warp = tid >> 5, lane = tid & 31;
    const int gid = lane >> 2, tig = lane & 3;

    build_B(Wl, sBhi, sBlo, tid);
    build_B(Wr, sB2hi, sB2lo, tid);
    __syncthreads();

    int r0 = blockIdx.x * 128 + warp * 16 + gid;
    int r1 = r0 + 8;
    const float* x0 = x + (size_t)(r0 < M ? r0 : M - 1) * 128;
    const float* x1 = x + (size_t)(r1 < M ? r1 : M - 1) * 128;

    float acc[4][4], acc2[4][4];
#pragma unroll
    for (int nt = 0; nt < 4; ++nt)
#pragma unroll
        for (int j = 0; j < 4; ++j) { acc[nt][j] = 0.f; acc2[nt][j] = 0.f; }

#pragma unroll
    for (int kt = 0; kt < 8; ++kt) {
        int c0 = kt * 16 + tig * 4;
        float4 f0 = *reinterpret_cast<const float4*>(x0 + c0);
        float4 f1 = *reinterpret_cast<const float4*>(x1 + c0);

        uint32_t ahi[4], alo[4];
        split_a(f0, ahi[0], alo[0], ahi[2], alo[2]);
        split_a(f1, ahi[1], alo[1], ahi[3], alo[3]);

#pragma unroll
        for (int nt = 0; nt < 4; ++nt) {
            uint32_t bh[2], bl[2], ch[2], cl[2];
            bh[0] = sBhi[kt][nt][lane][0];  bh[1] = sBhi[kt][nt][lane][1];
            bl[0] = sBlo[kt][nt][lane][0];  bl[1] = sBlo[kt][nt][lane][1];
            ch[0] = sB2hi[kt][nt][lane][0]; ch[1] = sB2hi[kt][nt][lane][1];
            cl[0] = sB2lo[kt][nt][lane][0]; cl[1] = sB2lo[kt][nt][lane][1];
            mma16816(acc[nt], ahi, bh);
            mma16816(acc[nt], ahi, bl);
            mma16816(acc[nt], alo, bh);
            mma16816(acc2[nt], ahi, ch);
            mma16816(acc2[nt], ahi, cl);
            mma16816(acc2[nt], alo, ch);
        }
    }

    if (r0 < M) {
        uint32_t* o = reinterpret_cast<uint32_t*>(obf + (size_t)r0 * 32) + tig;
#pragma unroll
        for (int nt = 0; nt < 4; ++nt) o[nt * 4] = pack_bf16x2(acc[nt][0], acc[nt][1]);
    }
    if (r1 < M) {
        uint32_t* o = reinterpret_cast<uint32_t*>(obf + (size_t)r1 * 32) + tig;
#pragma unroll
        for (int nt = 0; nt < 4; ++nt) o[nt * 4] = pack_bf16x2(acc[nt][2], acc[nt][3]);
    }
    if (r0 < N1) {
        float* o = oyr + (size_t)r0 * 32 + tig * 2;
#pragma unroll
        for (int nt = 0; nt < 4; ++nt)
            *reinterpret_cast<float2*>(o + nt * 8) = make_float2(acc2[nt][0], acc2[nt][1]);
    }
    if (r1 < N1) {
        float* o = oyr + (size_t)r1 * 32 + tig * 2;
#pragma unroll
        for (int nt = 0; nt < 4; ++nt)
            *reinterpret_cast<float2*>(o + nt * 8) = make_float2(acc2[nt][2], acc2[nt][3]);
    }
}

// ---------------- bf16 edge scatter: 8 threads/edge, 8-edge MLP ----------------
__global__ void scatter_bf16_kernel(const int* __restrict__ src, const int* __restrict__ dst,
                                    const __nv_bfloat16* __restrict__ feat,
                                    float* __restrict__ agg, float* __restrict__ cnt, int E) {
    int g = blockIdx.x * blockDim.x + threadIdx.x;
    int oct = E >> 3;
    int e = g >> 3, part = g & 7;
    if (e >= oct) return;
    int s[8], d[8];
#pragma unroll
    for (int j = 0; j < 8; ++j) {
        s[j] = __ldg(src + e + j * oct);
        d[j] = __ldg(dst + e + j * oct);
    }
    uint2 v[8];
#pragma unroll
    for (int j = 0; j < 8; ++j)
        v[j] = reinterpret_cast<const uint2*>(feat + (size_t)s[j] * 32)[part];
#pragma unroll
    for (int j = 0; j < 8; ++j) {
        float4 f = make_float4(bf_lo(v[j].x), bf_hi(v[j].x), bf_lo(v[j].y), bf_hi(v[j].y));
        atomicAdd(reinterpret_cast<float4*>(agg + (size_t)d[j] * 32 + part * 4), f);
    }
    if (part == 0) {
#pragma unroll
        for (int j = 0; j < 8; ++j) atomicAdd(cnt + d[j], 1.0f);
    }
}

// ---------------- fp32 edge scatter (8 threads/edge, 4-edge MLP) — for h/E1 ----------------
__global__ void scatter_kernel(const int* __restrict__ src, const int* __restrict__ dst,
                               const float* __restrict__ feat, float* __restrict__ agg,
                               float* __restrict__ cnt, int E) {
    int g = blockIdx.x * blockDim.x + threadIdx.x;
    int quart = E >> 2;
    int e = g >> 3, part = g & 7;
    if (e >= quart) return;
    int s[4], d[4];
#pragma unroll
    for (int j = 0; j < 4; ++j) {
        s[j] = __ldg(src + e + j * quart);
        d[j] = __ldg(dst + e + j * quart);
    }
    float4 v[4];
#pragma unroll
    for (int j = 0; j < 4; ++j)
        v[j] = *reinterpret_cast<const float4*>(feat + (size_t)s[j] * 32 + part * 4);
#pragma unroll
    for (int j = 0; j < 4; ++j)
        atomicAdd(reinterpret_cast<float4*>(agg + (size_t)d[j] * 32 + part * 4), v[j]);
    if (part == 0) {
#pragma unroll
        for (int j = 0; j < 4; ++j) atomicAdd(cnt + d[j], 1.0f);
    }
}

// ---------------- h = relu(agg0/cnt + yr), elementwise float4 ----------------
__global__ void relu_combine_kernel(const float* __restrict__ agg, const float* __restrict__ cnt,
                                    const float* __restrict__ yr, float* __restrict__ h) {
    int i = blockIdx.x * blockDim.x + threadIdx.x;   // float4 index, N1*8 total
    if (i >= N1 * 8) return;
    int row = i >> 3;
    float inv = 1.0f / fmaxf(__ldg(cnt + row), 1.0f);
    float4 a = reinterpret_cast<const float4*>(agg)[i];
    float4 v = reinterpret_cast<const float4*>(yr)[i];
    float4 r;
    r.x = fmaxf(fmaf(a.x, inv, v.x), 0.f);
    r.y = fmaxf(fmaf(a.y, inv, v.y), 0.f);
    r.z = fmaxf(fmaf(a.z, inv, v.z), 0.f);
    r.w = fmaxf(fmaf(a.w, inv, v.w), 0.f);
    reinterpret_cast<float4*>(h)[i] = r;
}

// ---------------- layer-1 combine ----------------
__global__ void final_kernel(const float* __restrict__ agg1, const float* __restrict__ cnt1,
                             const float* __restrict__ h, const float* __restrict__ W2l,
                             const float* __restrict__ W2r, float* __restrict__ out) {
    __shared__ float s2l[32 * 64];
    __shared__ float s2r[32 * 64];
    int tid = threadIdx.x;
    for (int idx = tid; idx < 2048; idx += 256) {
        int c = idx >> 5, k = idx & 31;
        s2l[k * 64 + c] = W2l[idx];
        s2r[k * 64 + c] = W2r[idx];
    }
    __syncthreads();
    int i = blockIdx.x * 4 + (tid >> 6);
    int c = tid & 63;
    float inv = 1.0f / fmaxf(__ldg(cnt1 + i), 1.0f);
    const float* ag = agg1 + (size_t)i * 32;
    const float* hh = h + (size_t)i * 32;
    float s = 0.f;
#pragma unroll
    for (int k = 0; k < 32; ++k)
        s = fmaf(__ldg(ag + k) * inv, s2l[k * 64 + c], fmaf(__ldg(hh + k), s2r[k * 64 + c], s));
    out[(size_t)i * 64 + c] = s;
}

extern "C" void kernel_launch(void* const* d_in, const int* in_sizes, int n_in,
                              void* d_out, int out_size) {
    const float* x   = (const float*)d_in[0];
    const float* W1l = (const float*)d_in[1];
    const float* W1r = (const float*)d_in[2];
    const float* W2l = (const float*)d_in[3];
    const float* W2r = (const float*)d_in[4];
    const int* es0   = (const int*)d_in[5];
    const int* ed0   = (const int*)d_in[6];
    const int* es1   = (const int*)d_in[7];
    const int* ed1   = (const int*)d_in[8];
    float* out = (float*)d_out;

    __nv_bfloat16* y;
    float *yr, *h, *agg0, *agg1, *cnt0, *cnt1;
    cudaGetSymbolAddress((void**)&y,    g_y);
    cudaGetSymbolAddress((void**)&yr,   g_yr);
    cudaGetSymbolAddress((void**)&h,    g_h);
    cudaGetSymbolAddress((void**)&agg0, g_agg0);
    cudaGetSymbolAddress((void**)&agg1, g_agg1);
    cudaGetSymbolAddress((void**)&cnt0, g_cnt0);
    cudaGetSymbolAddress((void**)&cnt1, g_cnt1);

    cudaMemsetAsync(agg0, 0, sizeof(float) * (size_t)N1 * 32, 0);
    cudaMemsetAsync(cnt0, 0, sizeof(float) * N1, 0);
    cudaMemsetAsync(agg1, 0, sizeof(float) * (size_t)N2 * 32, 0);
    cudaMemsetAsync(cnt1, 0, sizeof(float) * N2, 0);

    // DUAL: rows [0, SPLIT) -> y(bf16) + yr(fp32); plain: rows [SPLIT, N0)
    gemm_dual_kernel<<<SPLIT / 128, 256>>>(x, W1l, W1r, N0, y, yr);
    gemm_plain_kernel<<<(N0 - SPLIT) / 128, 256>>>(x, W1l, SPLIT, N0, y);
    // sum y over E0 edges
    scatter_bf16_kernel<<<(int)(((size_t)(E0 / 8) * 8 + 255) / 256), 256>>>(es0, ed0, y, agg0, cnt0, E0);
    // h = relu(agg0/cnt + yr)
    relu_combine_kernel<<<(N1 * 8 + 255) / 256, 256>>>(agg0, cnt0, yr, h);
    // layer-1 aggregation + combine
    scatter_kernel<<<(int)(((size_t)(E1 / 4) * 8 + 255) / 256), 256>>>(es1, ed1, h, agg1, cnt1, E1);
    final_kernel<<<N2 / 4, 256>>>(agg1, cnt1, h, W2l, W2r, out);
}

// round 17
// speedup vs baseline: 1.0723x; 1.0237x over previous
#include <cuda_runtime.h>
#include <cuda_bf16.h>
#include <cstdint>
#include <cstddef>

#define N0 2000000
#define N1 200000
#define N2 16384
#define E0 3200000
#define E1 262144
#define SPLIT 200064   // 1563*128; DUAL covers [0,SPLIT); plain covers [SPLIT,N0)

// Scratch (device globals: allocation-free rule)
__device__ __nv_bfloat16 g_y[(size_t)N0 * 32];   // 128 MB, bf16
__device__ float g_yr[(size_t)N1 * 32];          // x[:N1] @ W1r^T, fp32
__device__ float g_h[(size_t)N1 * 32];
__device__ float g_agg0[(size_t)N1 * 32];
__device__ float g_agg1[(size_t)N2 * 32];
__device__ float g_cnt0[N1];
__device__ float g_cnt1[N2];

__device__ __forceinline__ uint32_t pack_bf16x2(float lo, float hi) {
    uint32_t r;
    asm("cvt.rn.bf16x2.f32 %0, %1, %2;" : "=r"(r) : "f"(hi), "f"(lo));
    return r;
}
__device__ __forceinline__ float bf_lo(uint32_t w) { return __uint_as_float(w << 16); }
__device__ __forceinline__ float bf_hi(uint32_t w) { return __uint_as_float(w & 0xffff0000u); }

__device__ __forceinline__ void mma16816(float* c, const uint32_t* a, const uint32_t* b) {
    asm volatile(
        "mma.sync.aligned.m16n8k16.row.col.f32.bf16.bf16.f32 "
        "{%0,%1,%2,%3}, {%4,%5,%6,%7}, {%8,%9}, {%0,%1,%2,%3};"
        : "+f"(c[0]), "+f"(c[1]), "+f"(c[2]), "+f"(c[3])
        : "r"(a[0]), "r"(a[1]), "r"(a[2]), "r"(a[3]), "r"(b[0]), "r"(b[1]));
}

// Build permuted B fragment tables for one weight matrix
__device__ __forceinline__ void build_B(const float* __restrict__ W,
                                        uint32_t (*sBhi)[4][32][2], uint32_t (*sBlo)[4][32][2],
                                        int tid) {
    for (int i = tid; i < 1024; i += 256) {
        int l = i & 31, nt = (i >> 5) & 3, kt = i >> 7;
        int n = nt * 8 + (l >> 2);
        int k0 = kt * 16 + (l & 3) * 4;
        float4 w = *reinterpret_cast<const float4*>(W + n * 128 + k0);
        uint32_t h0 = pack_bf16x2(w.x, w.y);
        uint32_t h1 = pack_bf16x2(w.z, w.w);
        sBhi[kt][nt][l][0] = h0;
        sBhi[kt][nt][l][1] = h1;
        sBlo[kt][nt][l][0] = pack_bf16x2(w.x - bf_lo(h0), w.y - bf_hi(h0));
        sBlo[kt][nt][l][1] = pack_bf16x2(w.z - bf_lo(h1), w.w - bf_hi(h1));
    }
}

__device__ __forceinline__ void split_a(const float4& f, uint32_t& hi, uint32_t& lo2,
                                        uint32_t& hi2, uint32_t& lo3) {
    hi  = pack_bf16x2(f.x, f.y);
    hi2 = pack_bf16x2(f.z, f.w);
    lo2 = pack_bf16x2(f.x - bf_lo(hi),  f.y - bf_hi(hi));
    lo3 = pack_bf16x2(f.z - bf_lo(hi2), f.w - bf_hi(hi2));
}

// ---------------- plain GEMM (rows [base, base+grid*128)): y = x @ Wl^T (bf16) ----------------
// __launch_bounds__(256, 5): cap regs at 48 -> 5 CTAs/SM (62.5% occ) for latency hiding.
__global__ void __launch_bounds__(256, 5) gemm_plain_kernel(
    const float* __restrict__ x, const float* __restrict__ Wl,
    int base, int M, __nv_bfloat16* __restrict__ obf)
{
    __shared__ uint32_t sBhi[8][4][32][2];
    __shared__ uint32_t sBlo[8][4][32][2];

    const int tid = threadIdx.x;
    const int warp = tid >> 5, lane = tid & 31;
    const int gid = lane >> 2, tig = lane & 3;

    build_B(Wl, sBhi, sBlo, tid);
    __syncthreads();

    int r0 = base + blockIdx.x * 128 + warp * 16 + gid;
    int r1 = r0 + 8;
    const float* x0 = x + (size_t)(r0 < M ? r0 : M - 1) * 128;
    const float* x1 = x + (size_t)(r1 < M ? r1 : M - 1) * 128;

    float acc[4][4];
#pragma unroll
    for (int nt = 0; nt < 4; ++nt)
#pragma unroll
        for (int j = 0; j < 4; ++j) acc[nt][j] = 0.f;

#pragma unroll
    for (int kt = 0; kt < 8; ++kt) {
        int c0 = kt * 16 + tig * 4;
        float4 f0 = *reinterpret_cast<const float4*>(x0 + c0);
        float4 f1 = *reinterpret_cast<const float4*>(x1 + c0);

        uint32_t ahi[4], alo[4];
        split_a(f0, ahi[0], alo[0], ahi[2], alo[2]);
        split_a(f1, ahi[1], alo[1], ahi[3], alo[3]);

#pragma unroll
        for (int nt = 0; nt < 4; ++nt) {
            uint32_t bh[2], bl[2];
            bh[0] = sBhi[kt][nt][lane][0];
            bh[1] = sBhi[kt][nt][lane][1];
            bl[0] = sBlo[kt][nt][lane][0];
            bl[1] = sBlo[kt][nt][lane][1];
            mma16816(acc[nt], ahi, bh);
            mma16816(acc[nt], ahi, bl);
            mma16816(acc[nt], alo, bh);
        }
    }

    if (r0 < M) {
        uint32_t* o = reinterpret_cast<uint32_t*>(obf + (size_t)r0 * 32) + tig;
#pragma unroll
        for (int nt = 0; nt < 4; ++nt) o[nt * 4] = pack_bf16x2(acc[nt][0], acc[nt][1]);
    }
    if (r1 < M) {
        uint32_t* o = reinterpret_cast<uint32_t*>(obf + (size_t)r1 * 32) + tig;
#pragma unroll
        for (int nt = 0; nt < 4; ++nt) o[nt * 4] = pack_bf16x2(acc[nt][2], acc[nt][3]);
    }
}

// ---------------- DUAL GEMM (rows [0,SPLIT)): y bf16 + yr fp32 + zero agg/cnt ----------------
__global__ void __launch_bounds__(256) gemm_dual_kernel(
    const float* __restrict__ x, const float* __restrict__ Wl,
    const float* __restrict__ Wr, int M,
    __nv_bfloat16* __restrict__ obf, float* __restrict__ oyr,
    float* __restrict__ agg0, float* __restrict__ cnt0,
    float* __restrict__ agg1, float* __restrict__ cnt1)
{
    __shared__ uint32_t sBhi[8][4][32][2];
    __shared__ uint32_t sBlo[8][4][32][2];
    __shared__ uint32_t sB2hi[8][4][32][2];
    __shared__ uint32_t sB2lo[8][4][32][2];

    const int tid = threadIdx.x;
    const int warp = tid >> 5, lane = tid & 31;
    const int gid = lane >> 2, tig = lane & 3;

    build_B(Wl, sBhi, sBlo, tid);
    build_B(Wr, sB2hi, sB2lo, tid);
    __syncthreads();

    int r0 = blockIdx.x * 128 + warp * 16 + gid;
    int r1 = r0 + 8;
    const float* x0 = x + (size_t)(r0 < M ? r0 : M - 1) * 128;
    const float* x1 = x + (size_t)(r1 < M ? r1 : M - 1) * 128;

    // ---- fused zeroing of aggregation buffers (replaces serial memsets) ----
    const float2 z2 = make_float2(0.f, 0.f);
#pragma unroll
    for (int t = 0; t < 2; ++t) {
        int r = t == 0 ? r0 : r1;
        if (r < N1) {
            float* z = agg0 + (size_t)r * 32 + tig * 2;
#pragma unroll
            for (int nt = 0; nt < 4; ++nt) *reinterpret_cast<float2*>(z + nt * 8) = z2;
            if (tig == 0) cnt0[r] = 0.f;
        }
        if (r < N2) {
            float* z = agg1 + (size_t)r * 32 + tig * 2;
#pragma unroll
            for (int nt = 0; nt < 4; ++nt) *reinterpret_cast<float2*>(z + nt * 8) = z2;
            if (tig == 0) cnt1[r] = 0.f;
        }
    }

    float acc[4][4], acc2[4][4];
#pragma unroll
    for (int nt = 0; nt < 4; ++nt)
#pragma unroll
        for (int j = 0; j < 4; ++j) { acc[nt][j] = 0.f; acc2[nt][j] = 0.f; }

#pragma unroll
    for (int kt = 0; kt < 8; ++kt) {
        int c0 = kt * 16 + tig * 4;
        float4 f0 = *reinterpret_cast<const float4*>(x0 + c0);
        float4 f1 = *reinterpret_cast<const float4*>(x1 + c0);

        uint32_t ahi[4], alo[4];
        split_a(f0, ahi[0], alo[0], ahi[2], alo[2]);
        split_a(f1, ahi[1], alo[1], ahi[3], alo[3]);

#pragma unroll
        for (int nt = 0; nt < 4; ++nt) {
            uint32_t bh[2], bl[2], ch[2], cl[2];
            bh[0] = sBhi[kt][nt][lane][0];  bh[1] = sBhi[kt][nt][lane][1];
            bl[0] = sBlo[kt][nt][lane][0];  bl[1] = sBlo[kt][nt][lane][1];
            ch[0] = sB2hi[kt][nt][lane][0]; ch[1] = sB2hi[kt][nt][lane][1];
            cl[0] = sB2lo[kt][nt][lane][0]; cl[1] = sB2lo[kt][nt][lane][1];
            mma16816(acc[nt], ahi, bh);
            mma16816(acc[nt], ahi, bl);
            mma16816(acc[nt], alo, bh);
            mma16816(acc2[nt], ahi, ch);
            mma16816(acc2[nt], ahi, cl);
            mma16816(acc2[nt], alo, ch);
        }
    }

    if (r0 < M) {
        uint32_t* o = reinterpret_cast<uint32_t*>(obf + (size_t)r0 * 32) + tig;
#pragma unroll
        for (int nt = 0; nt < 4; ++nt) o[nt * 4] = pack_bf16x2(acc[nt][0], acc[nt][1]);
    }
    if (r1 < M) {
        uint32_t* o = reinterpret_cast<uint32_t*>(obf + (size_t)r1 * 32) + tig;
#pragma unroll
        for (int nt = 0; nt < 4; ++nt) o[nt * 4] = pack_bf16x2(acc[nt][2], acc[nt][3]);
    }
    if (r0 < N1) {
        float* o = oyr + (size_t)r0 * 32 + tig * 2;
#pragma unroll
        for (int nt = 0; nt < 4; ++nt)
            *reinterpret_cast<float2*>(o + nt * 8) = make_float2(acc2[nt][0], acc2[nt][1]);
    }
    if (r1 < N1) {
        float* o = oyr + (size_t)r1 * 32 + tig * 2;
#pragma unroll
        for (int nt = 0; nt < 4; ++nt)
            *reinterpret_cast<float2*>(o + nt * 8) = make_float2(acc2[nt][2], acc2[nt][3]);
    }
}

// ---------------- bf16 edge scatter: 8 threads/edge, 8-edge MLP ----------------
__global__ void scatter_bf16_kernel(const int* __restrict__ src, const int* __restrict__ dst,
                                    const __nv_bfloat16* __restrict__ feat,
                                    float* __restrict__ agg, float* __restrict__ cnt, int E) {
    int g = blockIdx.x * blockDim.x + threadIdx.x;
    int oct = E >> 3;
    int e = g >> 3, part = g & 7;
    if (e >= oct) return;
    int s[8], d[8];
#pragma unroll
    for (int j = 0; j < 8; ++j) {
        s[j] = __ldg(src + e + j * oct);
        d[j] = __ldg(dst + e + j * oct);
    }
    uint2 v[8];
#pragma unroll
    for (int j = 0; j < 8; ++j)
        v[j] = reinterpret_cast<const uint2*>(feat + (size_t)s[j] * 32)[part];
#pragma unroll
    for (int j = 0; j < 8; ++j) {
        float4 f = make_float4(bf_lo(v[j].x), bf_hi(v[j].x), bf_lo(v[j].y), bf_hi(v[j].y));
        atomicAdd(reinterpret_cast<float4*>(agg + (size_t)d[j] * 32 + part * 4), f);
    }
    if (part == 0) {
#pragma unroll
        for (int j = 0; j < 8; ++j) atomicAdd(cnt + d[j], 1.0f);
    }
}

// ---------------- fp32 edge scatter (8 threads/edge, 4-edge MLP) — for h/E1 ----------------
__global__ void scatter_kernel(const int* __restrict__ src, const int* __restrict__ dst,
                               const float* __restrict__ feat, float* __restrict__ agg,
                               float* __restrict__ cnt, int E) {
    int g = blockIdx.x * blockDim.x + threadIdx.x;
    int quart = E >> 2;
    int e = g >> 3, part = g & 7;
    if (e >= quart) return;
    int s[4], d[4];
#pragma unroll
    for (int j = 0; j < 4; ++j) {
        s[j] = __ldg(src + e + j * quart);
        d[j] = __ldg(dst + e + j * quart);
    }
    float4 v[4];
#pragma unroll
    for (int j = 0; j < 4; ++j)
        v[j] = *reinterpret_cast<const float4*>(feat + (size_t)s[j] * 32 + part * 4);
#pragma unroll
    for (int j = 0; j < 4; ++j)
        atomicAdd(reinterpret_cast<float4*>(agg + (size_t)d[j] * 32 + part * 4), v[j]);
    if (part == 0) {
#pragma unroll
        for (int j = 0; j < 4; ++j) atomicAdd(cnt + d[j], 1.0f);
    }
}

// ---------------- h = relu(agg0/cnt + yr), elementwise float4 ----------------
__global__ void relu_combine_kernel(const float* __restrict__ agg, const float* __restrict__ cnt,
                                    const float* __restrict__ yr, float* __restrict__ h) {
    int i = blockIdx.x * blockDim.x + threadIdx.x;   // float4 index, N1*8 total
    if (i >= N1 * 8) return;
    int row = i >> 3;
    float inv = 1.0f / fmaxf(__ldg(cnt + row), 1.0f);
    float4 a = reinterpret_cast<const float4*>(agg)[i];
    float4 v = reinterpret_cast<const float4*>(yr)[i];
    float4 r;
    r.x = fmaxf(fmaf(a.x, inv, v.x), 0.f);
    r.y = fmaxf(fmaf(a.y, inv, v.y), 0.f);
    r.z = fmaxf(fmaf(a.z, inv, v.z), 0.f);
    r.w = fmaxf(fmaf(a.w, inv, v.w), 0.f);
    reinterpret_cast<float4*>(h)[i] = r;
}

// ---------------- layer-1 combine ----------------
__global__ void final_kernel(const float* __restrict__ agg1, const float* __restrict__ cnt1,
                             const float* __restrict__ h, const float* __restrict__ W2l,
                             const float* __restrict__ W2r, float* __restrict__ out) {
    __shared__ float s2l[32 * 64];
    __shared__ float s2r[32 * 64];
    int tid = threadIdx.x;
    for (int idx = tid; idx < 2048; idx += 256) {
        int c = idx >> 5, k = idx & 31;
        s2l[k * 64 + c] = W2l[idx];
        s2r[k * 64 + c] = W2r[idx];
    }
    __syncthreads();
    int i = blockIdx.x * 4 + (tid >> 6);
    int c = tid & 63;
    float inv = 1.0f / fmaxf(__ldg(cnt1 + i), 1.0f);
    const float* ag = agg1 + (size_t)i * 32;
    const float* hh = h + (size_t)i * 32;
    float s = 0.f;
#pragma unroll
    for (int k = 0; k < 32; ++k)
        s = fmaf(__ldg(ag + k) * inv, s2l[k * 64 + c], fmaf(__ldg(hh + k), s2r[k * 64 + c], s));
    out[(size_t)i * 64 + c] = s;
}

extern "C" void kernel_launch(void* const* d_in, const int* in_sizes, int n_in,
                              void* d_out, int out_size) {
    const float* x   = (const float*)d_in[0];
    const float* W1l = (const float*)d_in[1];
    const float* W1r = (const float*)d_in[2];
    const float* W2l = (const float*)d_in[3];
    const float* W2r = (const float*)d_in[4];
    const int* es0   = (const int*)d_in[5];
    const int* ed0   = (const int*)d_in[6];
    const int* es1   = (const int*)d_in[7];
    const int* ed1   = (const int*)d_in[8];
    float* out = (float*)d_out;

    __nv_bfloat16* y;
    float *yr, *h, *agg0, *agg1, *cnt0, *cnt1;
    cudaGetSymbolAddress((void**)&y,    g_y);
    cudaGetSymbolAddress((void**)&yr,   g_yr);
    cudaGetSymbolAddress((void**)&h,    g_h);
    cudaGetSymbolAddress((void**)&agg0, g_agg0);
    cudaGetSymbolAddress((void**)&agg1, g_agg1);
    cudaGetSymbolAddress((void**)&cnt0, g_cnt0);
    cudaGetSymbolAddress((void**)&cnt1, g_cnt1);

    // DUAL: rows [0, SPLIT) -> y(bf16) + yr(fp32) + zero agg0/cnt0/agg1/cnt1 (fused memsets)
    gemm_dual_kernel<<<SPLIT / 128, 256>>>(x, W1l, W1r, N0, y, yr, agg0, cnt0, agg1, cnt1);
    // plain: rows [SPLIT, N0)
    gemm_plain_kernel<<<(N0 - SPLIT) / 128, 256>>>(x, W1l, SPLIT, N0, y);
    // sum y over E0 edges
    scatter_bf16_kernel<<<(int)(((size_t)(E0 / 8) * 8 + 255) / 256), 256>>>(es0, ed0, y, agg0, cnt0, E0);
    // h = relu(agg0/cnt + yr)
    relu_combine_kernel<<<(N1 * 8 + 255) / 256, 256>>>(agg0, cnt0, yr, h);
    // layer-1 aggregation + combine
    scatter_kernel<<<(int)(((size_t)(E1 / 4) * 8 + 255) / 256), 256>>>(es1, ed1, h, agg1, cnt1, E1);
    final_kernel<<<N2 / 4, 256>>>(agg1, cnt1, h, W2l, W2r, out);
}